// round 8
// baseline (speedup 1.0000x reference)
#include <cuda_runtime.h>
#include <cuda_bf16.h>
#include <cstdint>
#include <math.h>

// ---------------- problem constants ----------------
#define HN     64      // heads
#define PN     64      // head dim
#define GN_    8       // groups
#define NN     128     // state dim
#define CSN    256     // chunk size
#define HIDD   2048
#define INTER  4096    // H*P
#define GNN    1024    // G*N
#define CONVD  6144    // INTER + 2*G*N
#define PROJ   10304   // INTER + CONVD + H
#define LL     2048
#define BB     2
#define TT     4096    // B*L total tokens
#define NCH    16      // total chunks
#define DEADTH (-40.0f)

// ---------------- scratch (__device__ globals; no cudaMalloc allowed) ----------------
__device__ float g_zx   [(size_t)TT * PROJ];                 // in_proj output
__device__ float g_xbc  [(size_t)TT * CONVD];                // conv+silu output
__device__ float g_dt   [(size_t)HN * TT];                   // softplus dt, [h][t]
__device__ float g_dacs [(size_t)HN * TT];                   // per-chunk cumsum dt*A, [h][t]
__device__ float g_cb   [(size_t)NCH * GN_ * CSN * CSN];     // C.B^T per (chunk,group)
__device__ float g_state[(size_t)NCH * HN * PN * NN];
__device__ float g_prev [(size_t)NCH * HN * PN * NN];
__device__ float g_y    [(size_t)TT * INTER];
// tf32-rounded + k-block-permuted GEMM operands
__device__ float g_hr   [(size_t)TT * HIDD];
__device__ float g_w1r  [(size_t)PROJ * HIDD];
__device__ float g_w2r  [(size_t)HIDD * INTER];

// ---------------- helpers ----------------
__device__ __forceinline__ uint32_t f2tf(float x) {
    uint32_t r; asm("cvt.rna.tf32.f32 %0, %1;" : "=r"(r) : "f"(x)); return r;
}
// slot permutation within a 32-float k-block: k -> (k&3)*8 + (k>>3)*2 + ((k>>2)&1)
__device__ __forceinline__ int kslot(int k) {
    return (k & 3) * 8 + (k >> 3) * 2 + ((k >> 2) & 1);
}
__device__ __forceinline__ void mma_tf32(float* c, const uint32_t* a, const uint32_t* b) {
    asm volatile(
        "mma.sync.aligned.m16n8k8.row.col.f32.tf32.tf32.f32 "
        "{%0,%1,%2,%3},{%4,%5,%6,%7},{%8,%9},{%0,%1,%2,%3};\n"
        : "+f"(c[0]), "+f"(c[1]), "+f"(c[2]), "+f"(c[3])
        : "r"(a[0]), "r"(a[1]), "r"(a[2]), "r"(a[3]), "r"(b[0]), "r"(b[1]));
}
__device__ __forceinline__ void cpasync16(uint32_t sdst, const float* gsrc, int srcsz) {
    asm volatile("cp.async.cg.shared.global [%0], [%1], 16, %2;\n"
                 :: "r"(sdst), "l"(gsrc), "r"(srcsz));
}
__device__ __forceinline__ void cpcommit() { asm volatile("cp.async.commit_group;\n"); }
__device__ __forceinline__ void cpwait0()  { asm volatile("cp.async.wait_group 0;\n"); }

__device__ __forceinline__ float siluf(float v) { return v / (1.0f + __expf(-v)); }
__device__ __forceinline__ float softplusf(float x) {
    return (x > 20.0f) ? x : log1pf(__expf(x));
}

// ============================================================
// tf32 GEMM (mma.sync):  C[M,Nn] = A[M,K] * B[Nn,K]^T
// A, B pre-rounded to tf32 AND k-block-permuted (kslot).
// BM=128, BN=256, BK=32. 8 warps of 64x64 (2m x 4n). Double-buffered cp.async.
// Requires M%128==0, K%32==0. Nn edge guarded.
// ============================================================
#define GPIT 36
#define ASTG (128 * GPIT)
#define BSTG (256 * GPIT)
__global__ __launch_bounds__(256) void k_gemm(
    const float* __restrict__ A, const float* __restrict__ B, float* __restrict__ C,
    int Nn, int nk, int lda, int ldb, int ldc)
{
    extern __shared__ float sm[];
    float* sA = sm;                 // [2][128][GPIT]
    float* sB = sm + 2 * ASTG;      // [2][256][GPIT]

    const int tid  = threadIdx.x;
    const int lane = tid & 31;
    const int warp = tid >> 5;
    const int wm   = warp >> 2;     // 0..1  (64-row slab)
    const int wn   = warp & 3;      // 0..3  (64-col slab)
    const int bm0  = blockIdx.y * 128;
    const int bn0  = blockIdx.x * 256;

    float acc[4][8][4];
#pragma unroll
    for (int i = 0; i < 4; i++)
#pragma unroll
        for (int j = 0; j < 8; j++)
#pragma unroll
            for (int k = 0; k < 4; k++) acc[i][j][k] = 0.0f;

    // stage loader: k-tile kt -> buffer buf
    auto stage = [&](int buf, int kt) {
        int k0 = kt * 32;
        float* sa = sA + buf * ASTG;
        float* sb = sB + buf * BSTG;
        // A: 128 rows x 8 16B-chunks = 1024 chunks, 4 iters
#pragma unroll
        for (int i = 0; i < 4; i++) {
            int f = tid + i * 256;
            int r = f >> 3, c4 = (f & 7) * 4;
            const float* ga = A + (size_t)(bm0 + r) * lda + k0 + c4;
            cpasync16((uint32_t)__cvta_generic_to_shared(&sa[r * GPIT + c4]), ga, 16);
        }
        // B: 256 rows x 8 chunks = 2048 chunks, 8 iters (row-clamped, size-guarded)
#pragma unroll
        for (int i = 0; i < 8; i++) {
            int f = tid + i * 256;
            int r = f >> 3, c4 = (f & 7) * 4;
            int br = bn0 + r;
            int brc = br < (Nn - 1) ? br : (Nn - 1);
            const float* gb = B + (size_t)brc * ldb + k0 + c4;
            cpasync16((uint32_t)__cvta_generic_to_shared(&sb[r * GPIT + c4]), gb,
                      (br < Nn) ? 16 : 0);
        }
        cpcommit();
    };

    stage(0, 0);

    const int arow = lane >> 2;           // 0..7
    const int kcol = (lane & 3) * 8;      // slot-group base for this lane

    for (int kt = 0; kt < nk; kt++) {
        cpwait0();
        __syncthreads();
        if (kt + 1 < nk) stage((kt + 1) & 1, kt + 1);

        const float* a_ = sA + (kt & 1) * ASTG + wm * 64 * GPIT;
        const float* b_ = sB + (kt & 1) * BSTG + wn * 64 * GPIT;

#pragma unroll
        for (int kh = 0; kh < 2; kh++) {       // each kh covers 2 mma-k-steps
            int co = kcol + kh * 4;
            // A frags: 4 mi x 2 row-halves, one float4 each
            float4 av[4][2];
#pragma unroll
            for (int mi = 0; mi < 4; mi++) {
                int r0 = mi * 16 + arow;
                av[mi][0] = *(const float4*)&a_[r0 * GPIT + co];
                av[mi][1] = *(const float4*)&a_[(r0 + 8) * GPIT + co];
            }
            // B frags: 8 ni, one float4 each
            float4 bv[8];
#pragma unroll
            for (int ni = 0; ni < 8; ni++) {
                int n0 = ni * 8 + arow;
                bv[ni] = *(const float4*)&b_[n0 * GPIT + co];
            }
            // kk = 2*kh: use .x/.y ; kk = 2*kh+1: use .z/.w
#pragma unroll
            for (int q = 0; q < 2; q++) {
#pragma unroll
                for (int mi = 0; mi < 4; mi++) {
                    uint32_t af[4];
                    af[0] = __float_as_uint(q ? av[mi][0].z : av[mi][0].x);
                    af[1] = __float_as_uint(q ? av[mi][1].z : av[mi][1].x);
                    af[2] = __float_as_uint(q ? av[mi][0].w : av[mi][0].y);
                    af[3] = __float_as_uint(q ? av[mi][1].w : av[mi][1].y);
#pragma unroll
                    for (int ni = 0; ni < 8; ni++) {
                        uint32_t bf[2];
                        bf[0] = __float_as_uint(q ? bv[ni].z : bv[ni].x);
                        bf[1] = __float_as_uint(q ? bv[ni].w : bv[ni].y);
                        mma_tf32(acc[mi][ni], af, bf);
                    }
                }
            }
        }
        __syncthreads();
    }

    // epilogue
#pragma unroll
    for (int mi = 0; mi < 4; mi++) {
#pragma unroll
        for (int ni = 0; ni < 8; ni++) {
            int row = bm0 + wm * 64 + mi * 16 + arow;
            int col = bn0 + wn * 64 + ni * 8 + (lane & 3) * 2;
            if (col < Nn) {
                *(float2*)&C[(size_t)row * ldc + col] =
                    make_float2(acc[mi][ni][0], acc[mi][ni][1]);
                *(float2*)&C[(size_t)(row + 8) * ldc + col] =
                    make_float2(acc[mi][ni][2], acc[mi][ni][3]);
            }
        }
    }
}

// ============================================================
// tf32-rna round + k-block slot permutation (ld multiple of 32)
// ============================================================
__global__ __launch_bounds__(256) void k_round(
    const float* __restrict__ in, float* __restrict__ out, int n4)
{
    int i = blockIdx.x * 256 + threadIdx.x;
    int stride = gridDim.x * 256;
    for (; i < n4; i += stride) {
        int base = i * 4;
        float4 v = *(const float4*)&in[(size_t)base];
        int blk = base & ~31;
        out[(size_t)(blk | kslot((base + 0) & 31))] = __uint_as_float(f2tf(v.x));
        out[(size_t)(blk | kslot((base + 1) & 31))] = __uint_as_float(f2tf(v.y));
        out[(size_t)(blk | kslot((base + 2) & 31))] = __uint_as_float(f2tf(v.z));
        out[(size_t)(blk | kslot((base + 3) & 31))] = __uint_as_float(f2tf(v.w));
    }
}

// ============================================================
// conv1d (depthwise, causal K=4) + silu over xBC channels
// ============================================================
__global__ __launch_bounds__(256) void k_conv(
    const float* __restrict__ conv_w, const float* __restrict__ conv_b)
{
    int c = blockIdx.x * 256 + threadIdx.x;
    int t = blockIdx.y;
    int lt = t & (LL - 1);
    float w0 = conv_w[c * 4 + 0], w1 = conv_w[c * 4 + 1];
    float w2 = conv_w[c * 4 + 2], w3 = conv_w[c * 4 + 3];
    const float* zp = g_zx + (size_t)t * PROJ + INTER + c;
    float v = conv_b[c];
    if (lt >= 3) v += w0 * zp[-3 * (ptrdiff_t)PROJ];
    if (lt >= 2) v += w1 * zp[-2 * (ptrdiff_t)PROJ];
    if (lt >= 1) v += w2 * zp[-1 * (ptrdiff_t)PROJ];
    v += w3 * zp[0];
    g_xbc[(size_t)t * CONVD + c] = siluf(v);
}

// ============================================================
// dt softplus + per-chunk cumsum of dt*A. grid(16,8), 256 thr
// ============================================================
__global__ __launch_bounds__(256) void k_dtscan(
    const float* __restrict__ A_log, const float* __restrict__ dt_bias)
{
    int warp = threadIdx.x >> 5, lane = threadIdx.x & 31;
    int h = blockIdx.y * 8 + warp;
    int chunk = blockIdx.x;
    float Ah = -__expf(A_log[h]);
    float bias = dt_bias[h];
    int tbase = chunk * CSN + lane * 8;

    float pre[8];
    float run = 0.0f;
    float dts[8];
#pragma unroll
    for (int k = 0; k < 8; k++) {
        float raw = g_zx[(size_t)(tbase + k) * PROJ + (INTER + CONVD) + h];
        float dt = softplusf(raw + bias);
        dts[k] = dt;
        run += dt * Ah;
        pre[k] = run;
    }
    float tot = run;
#pragma unroll
    for (int off = 1; off < 32; off <<= 1) {
        float n = __shfl_up_sync(0xffffffffu, tot, off);
        if (lane >= off) tot += n;
    }
    float excl = tot - run;
#pragma unroll
    for (int k = 0; k < 8; k++) {
        g_dt  [(size_t)h * TT + tbase + k] = dts[k];
        g_dacs[(size_t)h * TT + tbase + k] = pre[k] + excl;
    }
}

// ============================================================
// CB[cg][i][j] = sum_n C[i,n]*B[j,n]   (lower-triangular 64x64 tiles)
// ============================================================
__global__ __launch_bounds__(256) void k_cb()
{
    int tile = blockIdx.x;
    int ti = tile >> 2, tj = tile & 3;
    if (ti < tj) return;
    int cg = blockIdx.y;
    int chunk = cg >> 3, g = cg & 7;

    __shared__ float sC[64][33];
    __shared__ float sB[64][33];

    int tid = threadIdx.x;
    int ty = tid >> 4, tx = tid & 15;
    float acc[4][4];
#pragma unroll
    for (int r = 0; r < 4; r++)
#pragma unroll
        for (int c = 0; c < 4; c++) acc[r][c] = 0.0f;

    const size_t cBase = (size_t)(chunk * CSN) * CONVD + INTER + GNN + (size_t)g * NN;
    const size_t bBase = (size_t)(chunk * CSN) * CONVD + INTER + (size_t)g * NN;

    for (int kt = 0; kt < 4; kt++) {
        int k0 = kt * 32;
#pragma unroll
        for (int i = 0; i < 2; i++) {
            int f = tid + i * 256;
            int r = f >> 3, kv = (f & 7) * 4;
            float4 cv = *(const float4*)&g_xbc[cBase + (size_t)(ti * 64 + r) * CONVD + k0 + kv];
            float4 bv = *(const float4*)&g_xbc[bBase + (size_t)(tj * 64 + r) * CONVD + k0 + kv];
            sC[r][kv + 0] = cv.x; sC[r][kv + 1] = cv.y;
            sC[r][kv + 2] = cv.z; sC[r][kv + 3] = cv.w;
            sB[r][kv + 0] = bv.x; sB[r][kv + 1] = bv.y;
            sB[r][kv + 2] = bv.z; sB[r][kv + 3] = bv.w;
        }
        __syncthreads();
#pragma unroll
        for (int kk = 0; kk < 32; kk++) {
            float a[4], b[4];
#pragma unroll
            for (int r = 0; r < 4; r++) a[r] = sC[ty * 4 + r][kk];
#pragma unroll
            for (int c = 0; c < 4; c++) b[c] = sB[tx * 4 + c][kk];
#pragma unroll
            for (int r = 0; r < 4; r++)
#pragma unroll
                for (int c = 0; c < 4; c++) acc[r][c] += a[r] * b[c];
        }
        __syncthreads();
    }
    float* out = g_cb + (size_t)cg * (CSN * CSN);
#pragma unroll
    for (int r = 0; r < 4; r++) {
        int i = ti * 64 + ty * 4 + r;
        int j = tj * 64 + tx * 4;
        *(float4*)&out[(size_t)i * CSN + j] = make_float4(acc[r][0], acc[r][1], acc[r][2], acc[r][3]);
    }
}

// ============================================================
// Y_diag + D*x  -> g_y.   grid (4 i-tiles, 16 chunks, 64 heads), 256 thr
// ============================================================
__global__ __launch_bounds__(256) void k_ydiag(const float* __restrict__ Dv)
{
    int it = blockIdx.x;
    int chunk = blockIdx.y;
    int h = blockIdx.z;
    int g = h >> 3;
    int i0 = it * 64;
    int tid = threadIdx.x;
    int ty = tid >> 4, tx = tid & 15;
    int p0 = tx * 4;

    __shared__ __align__(16) float sx[32][68];
    __shared__ float sM[32][65];
    __shared__ float sdj[32], sdtj[32], sdi[64];

    const float* dac = g_dacs + (size_t)h * TT + chunk * CSN;
    const float* dtp = g_dt   + (size_t)h * TT + chunk * CSN;
    const float* cbp = g_cb + (size_t)(chunk * 8 + g) * (CSN * CSN);

    if (tid < 64) sdi[tid] = dac[i0 + tid];
    __syncthreads();

    float acc[4][4];
#pragma unroll
    for (int r = 0; r < 4; r++)
#pragma unroll
        for (int c = 0; c < 4; c++) acc[r][c] = 0.0f;

    float dc_i0 = dac[i0];

    for (int jt = 2 * it + 1; jt >= 0; jt--) {
        int j0 = jt * 32;
        bool overlap = (j0 + 32 > i0);
        if (!overlap) {
            float d = dc_i0 - dac[j0 + 31];
            if (d < DEADTH) break;
        }
        if (tid < 32) { sdj[tid] = dac[j0 + tid]; sdtj[tid] = dtp[j0 + tid]; }
        __syncthreads();
#pragma unroll
        for (int i = 0; i < 2; i++) {
            int f = tid + i * 256;
            int j = f >> 4, pv = (f & 15) * 4;
            *(float4*)&sx[j][pv] =
                *(const float4*)&g_xbc[(size_t)(chunk * CSN + j0 + j) * CONVD + h * PN + pv];
        }
        __syncthreads();
        {
            int im = tid >> 2;
            int jb = (tid & 3) * 8;
            float di = sdi[im];
            int gi = i0 + im;
            float4 cb0 = *(const float4*)&cbp[(size_t)gi * CSN + j0 + jb];
            float4 cb1 = *(const float4*)&cbp[(size_t)gi * CSN + j0 + jb + 4];
            float cbv[8] = {cb0.x, cb0.y, cb0.z, cb0.w, cb1.x, cb1.y, cb1.z, cb1.w};
#pragma unroll
            for (int k = 0; k < 8; k++) {
                int j = jb + k;
                int gj = j0 + j;
                float m = 0.0f;
                if (gj <= gi) {
                    float d = fmaxf(di - sdj[j], -80.0f);
                    m = cbv[k] * __expf(d) * sdtj[j];
                }
                sM[j][im] = m;
            }
        }
        __syncthreads();
#pragma unroll 4
        for (int j = 0; j < 32; j++) {
            float4 xv = *(const float4*)&sx[j][p0];
#pragma unroll
            for (int r = 0; r < 4; r++) {
                float m = sM[j][ty * 4 + r];
                acc[r][0] += m * xv.x;
                acc[r][1] += m * xv.y;
                acc[r][2] += m * xv.z;
                acc[r][3] += m * xv.w;
            }
        }
        __syncthreads();
    }

    float Dh = Dv[h];
#pragma unroll
    for (int r = 0; r < 4; r++) {
        int i = i0 + ty * 4 + r;
        int t = chunk * CSN + i;
        float4 xv = *(const float4*)&g_xbc[(size_t)t * CONVD + h * PN + p0];
        float4 o = make_float4(acc[r][0] + Dh * xv.x, acc[r][1] + Dh * xv.y,
                               acc[r][2] + Dh * xv.z, acc[r][3] + Dh * xv.w);
        *(float4*)&g_y[(size_t)t * INTER + h * PN + p0] = o;
    }
}

// ============================================================
// states kernel
// ============================================================
__global__ __launch_bounds__(256) void k_states()
{
    int chunk = blockIdx.x, h = blockIdx.y, g = h >> 3;
    int tid = threadIdx.x;
    int ty = tid >> 4, tx = tid & 15;
    int p0 = ty * 4, n0 = tx * 8;

    __shared__ __align__(16) float sxw[32][68];
    __shared__ __align__(16) float sB[32][132];
    __shared__ float sw[32];

    const float* dac = g_dacs + (size_t)h * TT + chunk * CSN;
    const float* dtp = g_dt   + (size_t)h * TT + chunk * CSN;
    float dlast = dac[CSN - 1];

    float acc[4][8];
#pragma unroll
    for (int r = 0; r < 4; r++)
#pragma unroll
        for (int c = 0; c < 8; c++) acc[r][c] = 0.0f;

    for (int jt = 7; jt >= 0; jt--) {
        int j0 = jt * 32;
        if (dlast - dac[j0 + 31] < DEADTH) break;
        if (tid < 32)
            sw[tid] = __expf(fmaxf(dlast - dac[j0 + tid], -80.0f)) * dtp[j0 + tid];
        __syncthreads();
#pragma unroll
        for (int i = 0; i < 2; i++) {
            int f = tid + i * 256;
            int j = f >> 4, pv = (f & 15) * 4;
            float4 xv = *(const float4*)&g_xbc[(size_t)(chunk * CSN + j0 + j) * CONVD + h * PN + pv];
            float w = sw[j];
            xv.x *= w; xv.y *= w; xv.z *= w; xv.w *= w;
            *(float4*)&sxw[j][pv] = xv;
        }
#pragma unroll
        for (int i = 0; i < 4; i++) {
            int f = tid + i * 256;
            int j = f >> 5, nv = (f & 31) * 4;
            *(float4*)&sB[j][nv] =
                *(const float4*)&g_xbc[(size_t)(chunk * CSN + j0 + j) * CONVD + INTER + g * NN + nv];
        }
        __syncthreads();
#pragma unroll 2
        for (int j = 0; j < 32; j++) {
            float4 xv = *(const float4*)&sxw[j][p0];
            float4 b0 = *(const float4*)&sB[j][n0];
            float4 b1 = *(const float4*)&sB[j][n0 + 4];
            float xr[4] = {xv.x, xv.y, xv.z, xv.w};
            float bb[8] = {b0.x, b0.y, b0.z, b0.w, b1.x, b1.y, b1.z, b1.w};
#pragma unroll
            for (int r = 0; r < 4; r++)
#pragma unroll
                for (int c = 0; c < 8; c++) acc[r][c] += xr[r] * bb[c];
        }
        __syncthreads();
    }

    float* out = g_state + (size_t)(chunk * HN + h) * (PN * NN);
#pragma unroll
    for (int r = 0; r < 4; r++) {
        *(float4*)&out[(size_t)(p0 + r) * NN + n0]     = make_float4(acc[r][0], acc[r][1], acc[r][2], acc[r][3]);
        *(float4*)&out[(size_t)(p0 + r) * NN + n0 + 4] = make_float4(acc[r][4], acc[r][5], acc[r][6], acc[r][7]);
    }
}

// ============================================================
// inter-chunk scan
// ============================================================
__global__ __launch_bounds__(256) void k_scan()
{
    int b = blockIdx.x, h = blockIdx.y;
    int tid = threadIdx.x;
    float acc[32];
#pragma unroll
    for (int k = 0; k < 32; k++) acc[k] = 0.0f;
    for (int cl = 0; cl < 8; cl++) {
        int chunk = b * 8 + cl;
        size_t base = (size_t)(chunk * HN + h) * (PN * NN);
#pragma unroll
        for (int k = 0; k < 32; k++) g_prev[base + tid + k * 256] = acc[k];
        float decay = __expf(fmaxf(g_dacs[(size_t)h * TT + chunk * CSN + CSN - 1], -80.0f));
#pragma unroll
        for (int k = 0; k < 32; k++)
            acc[k] = decay * acc[k] + g_state[base + tid + k * 256];
    }
}

// ============================================================
// Y_off
// ============================================================
__global__ __launch_bounds__(256) void k_yoff()
{
    int chunk = blockIdx.x;
    if ((chunk & 7) == 0) return;
    int h = blockIdx.y, g = h >> 3;
    const float* dac = g_dacs + (size_t)h * TT + chunk * CSN;
    if (dac[0] < DEADTH) return;

    __shared__ __align__(16) float sPT[128][64];
    __shared__ __align__(16) float sC[16][128];

    int tid = threadIdx.x;
    size_t pbase = (size_t)(chunk * HN + h) * (PN * NN);
#pragma unroll
    for (int k = 0; k < 32; k++) {
        int idx = tid + k * 256;
        int p = idx >> 7, n = idx & 127;
        sPT[n][p] = g_prev[pbase + idx];
    }
    __syncthreads();

    int im = tid >> 4;
    int p0 = (tid & 15) * 4;

    for (int it = 0; it < 16; it++) {
        int i0 = it * 16;
        if (dac[i0] < DEADTH) break;
#pragma unroll
        for (int k = 0; k < 2; k++) {
            int f = tid + k * 256;
            int i = f >> 5, nv = (f & 31) * 4;
            *(float4*)&sC[i][nv] =
                *(const float4*)&g_xbc[(size_t)(chunk * CSN + i0 + i) * CONVD + INTER + GNN + g * NN + nv];
        }
        __syncthreads();
        float4 acc = make_float4(0.f, 0.f, 0.f, 0.f);
#pragma unroll 4
        for (int n = 0; n < 128; n++) {
            float cv = sC[im][n];
            float4 pv = *(const float4*)&sPT[n][p0];
            acc.x += cv * pv.x; acc.y += cv * pv.y;
            acc.z += cv * pv.z; acc.w += cv * pv.w;
        }
        float e = __expf(fmaxf(dac[i0 + im], -80.0f));
        int t = chunk * CSN + i0 + im;
        float4 o = *(float4*)&g_y[(size_t)t * INTER + h * PN + p0];
        o.x += e * acc.x; o.y += e * acc.y; o.z += e * acc.z; o.w += e * acc.w;
        *(float4*)&g_y[(size_t)t * INTER + h * PN + p0] = o;
        __syncthreads();
    }
}

// ============================================================
// RMSNorm * silu(z) gate, in place on g_y.
// Output is tf32-rna rounded AND kslot-permuted (GEMM2 A operand).
// Safe in-place: each 32-float block handled by one warp instruction pair.
// ============================================================
__global__ __launch_bounds__(256) void k_norm(const float* __restrict__ norm_w)
{
    int t = blockIdx.x;
    int tid = threadIdx.x;
    __shared__ float red[8];
    float* yp = g_y + (size_t)t * INTER;
    const float* zp = g_zx + (size_t)t * PROJ;

    float ss = 0.0f;
#pragma unroll
    for (int k = 0; k < 16; k++) {
        float v = yp[tid + k * 256];
        ss += v * v;
    }
#pragma unroll
    for (int off = 16; off >= 1; off >>= 1) ss += __shfl_xor_sync(0xffffffffu, ss, off);
    if ((tid & 31) == 0) red[tid >> 5] = ss;
    __syncthreads();
    if (tid == 0) {
        float tot = 0.0f;
#pragma unroll
        for (int i = 0; i < 8; i++) tot += red[i];
        red[0] = rsqrtf(tot * (1.0f / INTER) + 1e-5f);
    }
    __syncthreads();
    float rinv = red[0];
#pragma unroll
    for (int k = 0; k < 16; k++) {
        int c = tid + k * 256;
        float v = yp[c];
        float z = zp[c];
        float o = norm_w[c] * v * rinv * siluf(z);
        yp[(c & ~31) | kslot(c & 31)] = __uint_as_float(f2tf(o));
    }
}

// ============================================================
// launch
// ============================================================
extern "C" void kernel_launch(void* const* d_in, const int* in_sizes, int n_in,
                              void* d_out, int out_size)
{
    const float* hidden   = (const float*)d_in[0];
    const float* in_w     = (const float*)d_in[1];
    const float* conv_w   = (const float*)d_in[2];
    const float* conv_b   = (const float*)d_in[3];
    const float* dt_bias  = (const float*)d_in[4];
    const float* A_log    = (const float*)d_in[5];
    const float* Dv       = (const float*)d_in[6];
    const float* norm_w   = (const float*)d_in[7];
    const float* out_w    = (const float*)d_in[8];
    float* outp = (float*)d_out;

    float* zx;  cudaGetSymbolAddress((void**)&zx,  g_zx);
    float* yy;  cudaGetSymbolAddress((void**)&yy,  g_y);
    float* hr;  cudaGetSymbolAddress((void**)&hr,  g_hr);
    float* w1r; cudaGetSymbolAddress((void**)&w1r, g_w1r);
    float* w2r; cudaGetSymbolAddress((void**)&w2r, g_w2r);

    static int smem_set = 0;
    const int gemm_smem = 2 * (ASTG + BSTG) * (int)sizeof(float);  // 110,592 B
    if (!smem_set) {
        cudaFuncSetAttribute(k_gemm, cudaFuncAttributeMaxDynamicSharedMemorySize, gemm_smem);
        smem_set = 1;
    }

    // 0. pre-round + k-block-permute GEMM operands
    k_round<<<2048, 256>>>(hidden, hr,  (TT * HIDD) / 4);
    k_round<<<4096, 256>>>(in_w,  w1r, (PROJ * HIDD) / 4);
    k_round<<<2048, 256>>>(out_w, w2r, (HIDD * INTER) / 4);

    // 1. in_proj:  zx[T, PROJ] = hr @ w1r^T
    {
        dim3 grid((PROJ + 255) / 256, TT / 128);
        k_gemm<<<grid, 256, gemm_smem>>>(hr, w1r, zx, PROJ, HIDD / 32, HIDD, HIDD, PROJ);
    }
    // 2. conv + silu
    k_conv<<<dim3(CONVD / 256, TT), 256>>>(conv_w, conv_b);
    // 3. dt softplus + cumsum
    k_dtscan<<<dim3(NCH, 8), 256>>>(A_log, dt_bias);
    // 4. CB
    k_cb<<<dim3(16, NCH * GN_), 256>>>();
    // 5. Y_diag + D*x
    k_ydiag<<<dim3(4, NCH, HN), 256>>>(Dv);
    // 6. states
    k_states<<<dim3(NCH, HN), 256>>>();
    // 7. scan
    k_scan<<<dim3(BB, HN), 256>>>();
    // 8. Y_off
    k_yoff<<<dim3(NCH, HN), 256>>>();
    // 9. rmsnorm + gate (writes rounded+permuted y)
    k_norm<<<TT, 256>>>(norm_w);
    // 10. out_proj: out[T, HIDD] = y @ w2r^T
    {
        dim3 grid(HIDD / 256, TT / 128);
        k_gemm<<<grid, 256, gemm_smem>>>(yy, w2r, outp, HIDD, INTER / 32, INTER, INTER, HIDD);
    }
    (void)in_sizes; (void)n_in; (void)out_size;
}

// round 9
// speedup vs baseline: 1.0453x; 1.0453x over previous
#include <cuda_runtime.h>
#include <cuda_bf16.h>
#include <cstdint>
#include <math.h>

// ---------------- problem constants ----------------
#define HN     64      // heads
#define PN     64      // head dim
#define GN_    8       // groups
#define NN     128     // state dim
#define CSN    256     // chunk size
#define HIDD   2048
#define INTER  4096    // H*P
#define GNN    1024    // G*N
#define CONVD  6144    // INTER + 2*G*N
#define PROJ   10304   // INTER + CONVD + H
#define LL     2048
#define BB     2
#define TT     4096    // B*L total tokens
#define NCH    16      // total chunks
#define DEADTH (-40.0f)

// ---------------- scratch (__device__ globals; no cudaMalloc allowed) ----------------
__device__ float g_zx   [(size_t)TT * PROJ];                 // in_proj output
__device__ float g_xbc  [(size_t)TT * CONVD];                // conv+silu output
__device__ float g_dt   [(size_t)HN * TT];                   // softplus dt, [h][t]
__device__ float g_dacs [(size_t)HN * TT];                   // per-chunk cumsum dt*A, [h][t]
__device__ float g_cb   [(size_t)NCH * GN_ * CSN * CSN];     // C.B^T per (chunk,group)
__device__ float g_state[(size_t)NCH * HN * PN * NN];
__device__ float g_prev [(size_t)NCH * HN * PN * NN];
__device__ float g_y    [(size_t)TT * INTER];
// tf32-rounded + k-block-permuted GEMM operands
__device__ float g_hr   [(size_t)TT * HIDD];
__device__ float g_w1r  [(size_t)PROJ * HIDD];
__device__ float g_w2r  [(size_t)HIDD * INTER];

// ---------------- helpers ----------------
__device__ __forceinline__ uint32_t f2tf(float x) {
    uint32_t r; asm("cvt.rna.tf32.f32 %0, %1;" : "=r"(r) : "f"(x)); return r;
}
// slot permutation within a 32-float k-block: k -> (k&3)*8 + (k>>3)*2 + ((k>>2)&1)
__device__ __forceinline__ int kslot(int k) {
    return (k & 3) * 8 + (k >> 3) * 2 + ((k >> 2) & 1);
}
__device__ __forceinline__ void mma_tf32(float* c, const uint32_t* a, const uint32_t* b) {
    asm volatile(
        "mma.sync.aligned.m16n8k8.row.col.f32.tf32.tf32.f32 "
        "{%0,%1,%2,%3},{%4,%5,%6,%7},{%8,%9},{%0,%1,%2,%3};\n"
        : "+f"(c[0]), "+f"(c[1]), "+f"(c[2]), "+f"(c[3])
        : "r"(a[0]), "r"(a[1]), "r"(a[2]), "r"(a[3]), "r"(b[0]), "r"(b[1]));
}
__device__ __forceinline__ void cpasync16(uint32_t sdst, const float* gsrc, int srcsz) {
    asm volatile("cp.async.cg.shared.global [%0], [%1], 16, %2;\n"
                 :: "r"(sdst), "l"(gsrc), "r"(srcsz));
}
__device__ __forceinline__ void cpcommit() { asm volatile("cp.async.commit_group;\n"); }
__device__ __forceinline__ void cpwait0()  { asm volatile("cp.async.wait_group 0;\n"); }

__device__ __forceinline__ float siluf(float v) { return v / (1.0f + __expf(-v)); }
__device__ __forceinline__ float softplusf(float x) {
    return (x > 20.0f) ? x : log1pf(__expf(x));
}

// ============================================================
// tf32 GEMM (mma.sync):  C[M,Nn] = A[M,K] * B[Nn,K]^T
// A, B pre-rounded to tf32 AND k-block-permuted (kslot).
// BM=128, BN=256, BK=32. 8 warps of 64x64 (2m x 4n). Double-buffered cp.async.
// Warp-phase-staggered kh order so LDS bursts and HMMA streams overlap
// across warps within each SMSP; single barrier per k-tile.
// ============================================================
#define GPIT 36
#define ASTG (128 * GPIT)
#define BSTG (256 * GPIT)
__global__ __launch_bounds__(256) void k_gemm(
    const float* __restrict__ A, const float* __restrict__ B, float* __restrict__ C,
    int Nn, int nk, int lda, int ldb, int ldc)
{
    extern __shared__ float sm[];
    float* sA = sm;                 // [2][128][GPIT]
    float* sB = sm + 2 * ASTG;      // [2][256][GPIT]

    const int tid  = threadIdx.x;
    const int lane = tid & 31;
    const int warp = tid >> 5;
    const int wm   = warp >> 2;     // 0..1  (64-row slab)
    const int wn   = warp & 3;      // 0..3  (64-col slab)
    const int bm0  = blockIdx.y * 128;
    const int bn0  = blockIdx.x * 256;

    float acc[4][8][4];
#pragma unroll
    for (int i = 0; i < 4; i++)
#pragma unroll
        for (int j = 0; j < 8; j++)
#pragma unroll
            for (int k = 0; k < 4; k++) acc[i][j][k] = 0.0f;

    // stage loader: k-tile kt -> buffer buf
    auto stage = [&](int buf, int kt) {
        int k0 = kt * 32;
        float* sa = sA + buf * ASTG;
        float* sb = sB + buf * BSTG;
#pragma unroll
        for (int i = 0; i < 4; i++) {
            int f = tid + i * 256;
            int r = f >> 3, c4 = (f & 7) * 4;
            const float* ga = A + (size_t)(bm0 + r) * lda + k0 + c4;
            cpasync16((uint32_t)__cvta_generic_to_shared(&sa[r * GPIT + c4]), ga, 16);
        }
#pragma unroll
        for (int i = 0; i < 8; i++) {
            int f = tid + i * 256;
            int r = f >> 3, c4 = (f & 7) * 4;
            int br = bn0 + r;
            int brc = br < (Nn - 1) ? br : (Nn - 1);
            const float* gb = B + (size_t)brc * ldb + k0 + c4;
            cpasync16((uint32_t)__cvta_generic_to_shared(&sb[r * GPIT + c4]), gb,
                      (br < Nn) ? 16 : 0);
        }
        cpcommit();
    };

    stage(0, 0);

    const int arow = lane >> 2;           // 0..7
    const int kcol = (lane & 3) * 8;      // slot-group base for this lane
    const int kh0  = warp & 1;            // phase stagger: odd warps start at kh=1

    for (int kt = 0; kt < nk; kt++) {
        cpwait0();
        __syncthreads();                  // single barrier per k-tile
        if (kt + 1 < nk) stage((kt + 1) & 1, kt + 1);

        const float* a_ = sA + (kt & 1) * ASTG + wm * 64 * GPIT;
        const float* b_ = sB + (kt & 1) * BSTG + wn * 64 * GPIT;

#pragma unroll
        for (int khi = 0; khi < 2; khi++) {
            const int kh = khi ^ kh0;     // even warps: 0,1 ; odd warps: 1,0
            int co = kcol + kh * 4;
            float4 av[4][2];
#pragma unroll
            for (int mi = 0; mi < 4; mi++) {
                int r0 = mi * 16 + arow;
                av[mi][0] = *(const float4*)&a_[r0 * GPIT + co];
                av[mi][1] = *(const float4*)&a_[(r0 + 8) * GPIT + co];
            }
            float4 bv[8];
#pragma unroll
            for (int ni = 0; ni < 8; ni++) {
                int n0 = ni * 8 + arow;
                bv[ni] = *(const float4*)&b_[n0 * GPIT + co];
            }
#pragma unroll
            for (int q = 0; q < 2; q++) {
#pragma unroll
                for (int mi = 0; mi < 4; mi++) {
                    uint32_t af[4];
                    af[0] = __float_as_uint(q ? av[mi][0].z : av[mi][0].x);
                    af[1] = __float_as_uint(q ? av[mi][1].z : av[mi][1].x);
                    af[2] = __float_as_uint(q ? av[mi][0].w : av[mi][0].y);
                    af[3] = __float_as_uint(q ? av[mi][1].w : av[mi][1].y);
#pragma unroll
                    for (int ni = 0; ni < 8; ni++) {
                        uint32_t bf[2];
                        bf[0] = __float_as_uint(q ? bv[ni].z : bv[ni].x);
                        bf[1] = __float_as_uint(q ? bv[ni].w : bv[ni].y);
                        mma_tf32(acc[mi][ni], af, bf);
                    }
                }
            }
        }
        // no trailing barrier: next iteration's barrier orders buffer reuse
    }

    // epilogue
#pragma unroll
    for (int mi = 0; mi < 4; mi++) {
#pragma unroll
        for (int ni = 0; ni < 8; ni++) {
            int row = bm0 + wm * 64 + mi * 16 + arow;
            int col = bn0 + wn * 64 + ni * 8 + (lane & 3) * 2;
            if (col < Nn) {
                *(float2*)&C[(size_t)row * ldc + col] =
                    make_float2(acc[mi][ni][0], acc[mi][ni][1]);
                *(float2*)&C[(size_t)(row + 8) * ldc + col] =
                    make_float2(acc[mi][ni][2], acc[mi][ni][3]);
            }
        }
    }
}

// ============================================================
// tf32-rna round + k-block slot permutation (ld multiple of 32)
// ============================================================
__global__ __launch_bounds__(256) void k_round(
    const float* __restrict__ in, float* __restrict__ out, int n4)
{
    int i = blockIdx.x * 256 + threadIdx.x;
    int stride = gridDim.x * 256;
    for (; i < n4; i += stride) {
        int base = i * 4;
        float4 v = *(const float4*)&in[(size_t)base];
        int blk = base & ~31;
        out[(size_t)(blk | kslot((base + 0) & 31))] = __uint_as_float(f2tf(v.x));
        out[(size_t)(blk | kslot((base + 1) & 31))] = __uint_as_float(f2tf(v.y));
        out[(size_t)(blk | kslot((base + 2) & 31))] = __uint_as_float(f2tf(v.z));
        out[(size_t)(blk | kslot((base + 3) & 31))] = __uint_as_float(f2tf(v.w));
    }
}

// ============================================================
// conv1d (depthwise, causal K=4) + silu over xBC channels
// ============================================================
__global__ __launch_bounds__(256) void k_conv(
    const float* __restrict__ conv_w, const float* __restrict__ conv_b)
{
    int c = blockIdx.x * 256 + threadIdx.x;
    int t = blockIdx.y;
    int lt = t & (LL - 1);
    float w0 = conv_w[c * 4 + 0], w1 = conv_w[c * 4 + 1];
    float w2 = conv_w[c * 4 + 2], w3 = conv_w[c * 4 + 3];
    const float* zp = g_zx + (size_t)t * PROJ + INTER + c;
    float v = conv_b[c];
    if (lt >= 3) v += w0 * zp[-3 * (ptrdiff_t)PROJ];
    if (lt >= 2) v += w1 * zp[-2 * (ptrdiff_t)PROJ];
    if (lt >= 1) v += w2 * zp[-1 * (ptrdiff_t)PROJ];
    v += w3 * zp[0];
    g_xbc[(size_t)t * CONVD + c] = siluf(v);
}

// ============================================================
// dt softplus + per-chunk cumsum of dt*A. grid(16,8), 256 thr
// ============================================================
__global__ __launch_bounds__(256) void k_dtscan(
    const float* __restrict__ A_log, const float* __restrict__ dt_bias)
{
    int warp = threadIdx.x >> 5, lane = threadIdx.x & 31;
    int h = blockIdx.y * 8 + warp;
    int chunk = blockIdx.x;
    float Ah = -__expf(A_log[h]);
    float bias = dt_bias[h];
    int tbase = chunk * CSN + lane * 8;

    float pre[8];
    float run = 0.0f;
    float dts[8];
#pragma unroll
    for (int k = 0; k < 8; k++) {
        float raw = g_zx[(size_t)(tbase + k) * PROJ + (INTER + CONVD) + h];
        float dt = softplusf(raw + bias);
        dts[k] = dt;
        run += dt * Ah;
        pre[k] = run;
    }
    float tot = run;
#pragma unroll
    for (int off = 1; off < 32; off <<= 1) {
        float n = __shfl_up_sync(0xffffffffu, tot, off);
        if (lane >= off) tot += n;
    }
    float excl = tot - run;
#pragma unroll
    for (int k = 0; k < 8; k++) {
        g_dt  [(size_t)h * TT + tbase + k] = dts[k];
        g_dacs[(size_t)h * TT + tbase + k] = pre[k] + excl;
    }
}

// ============================================================
// CB[cg][i][j] = sum_n C[i,n]*B[j,n]   (lower-triangular 64x64 tiles)
// ============================================================
__global__ __launch_bounds__(256) void k_cb()
{
    int tile = blockIdx.x;
    int ti = tile >> 2, tj = tile & 3;
    if (ti < tj) return;
    int cg = blockIdx.y;
    int chunk = cg >> 3, g = cg & 7;

    __shared__ float sC[64][33];
    __shared__ float sB[64][33];

    int tid = threadIdx.x;
    int ty = tid >> 4, tx = tid & 15;
    float acc[4][4];
#pragma unroll
    for (int r = 0; r < 4; r++)
#pragma unroll
        for (int c = 0; c < 4; c++) acc[r][c] = 0.0f;

    const size_t cBase = (size_t)(chunk * CSN) * CONVD + INTER + GNN + (size_t)g * NN;
    const size_t bBase = (size_t)(chunk * CSN) * CONVD + INTER + (size_t)g * NN;

    for (int kt = 0; kt < 4; kt++) {
        int k0 = kt * 32;
#pragma unroll
        for (int i = 0; i < 2; i++) {
            int f = tid + i * 256;
            int r = f >> 3, kv = (f & 7) * 4;
            float4 cv = *(const float4*)&g_xbc[cBase + (size_t)(ti * 64 + r) * CONVD + k0 + kv];
            float4 bv = *(const float4*)&g_xbc[bBase + (size_t)(tj * 64 + r) * CONVD + k0 + kv];
            sC[r][kv + 0] = cv.x; sC[r][kv + 1] = cv.y;
            sC[r][kv + 2] = cv.z; sC[r][kv + 3] = cv.w;
            sB[r][kv + 0] = bv.x; sB[r][kv + 1] = bv.y;
            sB[r][kv + 2] = bv.z; sB[r][kv + 3] = bv.w;
        }
        __syncthreads();
#pragma unroll
        for (int kk = 0; kk < 32; kk++) {
            float a[4], b[4];
#pragma unroll
            for (int r = 0; r < 4; r++) a[r] = sC[ty * 4 + r][kk];
#pragma unroll
            for (int c = 0; c < 4; c++) b[c] = sB[tx * 4 + c][kk];
#pragma unroll
            for (int r = 0; r < 4; r++)
#pragma unroll
                for (int c = 0; c < 4; c++) acc[r][c] += a[r] * b[c];
        }
        __syncthreads();
    }
    float* out = g_cb + (size_t)cg * (CSN * CSN);
#pragma unroll
    for (int r = 0; r < 4; r++) {
        int i = ti * 64 + ty * 4 + r;
        int j = tj * 64 + tx * 4;
        *(float4*)&out[(size_t)i * CSN + j] = make_float4(acc[r][0], acc[r][1], acc[r][2], acc[r][3]);
    }
}

// ============================================================
// Y_diag + D*x  -> g_y.   grid (4 i-tiles, 16 chunks, 64 heads), 256 thr
// ============================================================
__global__ __launch_bounds__(256) void k_ydiag(const float* __restrict__ Dv)
{
    int it = blockIdx.x;
    int chunk = blockIdx.y;
    int h = blockIdx.z;
    int g = h >> 3;
    int i0 = it * 64;
    int tid = threadIdx.x;
    int ty = tid >> 4, tx = tid & 15;
    int p0 = tx * 4;

    __shared__ __align__(16) float sx[32][68];
    __shared__ float sM[32][65];
    __shared__ float sdj[32], sdtj[32], sdi[64];

    const float* dac = g_dacs + (size_t)h * TT + chunk * CSN;
    const float* dtp = g_dt   + (size_t)h * TT + chunk * CSN;
    const float* cbp = g_cb + (size_t)(chunk * 8 + g) * (CSN * CSN);

    if (tid < 64) sdi[tid] = dac[i0 + tid];
    __syncthreads();

    float acc[4][4];
#pragma unroll
    for (int r = 0; r < 4; r++)
#pragma unroll
        for (int c = 0; c < 4; c++) acc[r][c] = 0.0f;

    float dc_i0 = dac[i0];

    for (int jt = 2 * it + 1; jt >= 0; jt--) {
        int j0 = jt * 32;
        bool overlap = (j0 + 32 > i0);
        if (!overlap) {
            float d = dc_i0 - dac[j0 + 31];
            if (d < DEADTH) break;
        }
        if (tid < 32) { sdj[tid] = dac[j0 + tid]; sdtj[tid] = dtp[j0 + tid]; }
        __syncthreads();
#pragma unroll
        for (int i = 0; i < 2; i++) {
            int f = tid + i * 256;
            int j = f >> 4, pv = (f & 15) * 4;
            *(float4*)&sx[j][pv] =
                *(const float4*)&g_xbc[(size_t)(chunk * CSN + j0 + j) * CONVD + h * PN + pv];
        }
        __syncthreads();
        {
            int im = tid >> 2;
            int jb = (tid & 3) * 8;
            float di = sdi[im];
            int gi = i0 + im;
            float4 cb0 = *(const float4*)&cbp[(size_t)gi * CSN + j0 + jb];
            float4 cb1 = *(const float4*)&cbp[(size_t)gi * CSN + j0 + jb + 4];
            float cbv[8] = {cb0.x, cb0.y, cb0.z, cb0.w, cb1.x, cb1.y, cb1.z, cb1.w};
#pragma unroll
            for (int k = 0; k < 8; k++) {
                int j = jb + k;
                int gj = j0 + j;
                float m = 0.0f;
                if (gj <= gi) {
                    float d = fmaxf(di - sdj[j], -80.0f);
                    m = cbv[k] * __expf(d) * sdtj[j];
                }
                sM[j][im] = m;
            }
        }
        __syncthreads();
#pragma unroll 4
        for (int j = 0; j < 32; j++) {
            float4 xv = *(const float4*)&sx[j][p0];
#pragma unroll
            for (int r = 0; r < 4; r++) {
                float m = sM[j][ty * 4 + r];
                acc[r][0] += m * xv.x;
                acc[r][1] += m * xv.y;
                acc[r][2] += m * xv.z;
                acc[r][3] += m * xv.w;
            }
        }
        __syncthreads();
    }

    float Dh = Dv[h];
#pragma unroll
    for (int r = 0; r < 4; r++) {
        int i = i0 + ty * 4 + r;
        int t = chunk * CSN + i;
        float4 xv = *(const float4*)&g_xbc[(size_t)t * CONVD + h * PN + p0];
        float4 o = make_float4(acc[r][0] + Dh * xv.x, acc[r][1] + Dh * xv.y,
                               acc[r][2] + Dh * xv.z, acc[r][3] + Dh * xv.w);
        *(float4*)&g_y[(size_t)t * INTER + h * PN + p0] = o;
    }
}

// ============================================================
// states kernel
// ============================================================
__global__ __launch_bounds__(256) void k_states()
{
    int chunk = blockIdx.x, h = blockIdx.y, g = h >> 3;
    int tid = threadIdx.x;
    int ty = tid >> 4, tx = tid & 15;
    int p0 = ty * 4, n0 = tx * 8;

    __shared__ __align__(16) float sxw[32][68];
    __shared__ __align__(16) float sB[32][132];
    __shared__ float sw[32];

    const float* dac = g_dacs + (size_t)h * TT + chunk * CSN;
    const float* dtp = g_dt   + (size_t)h * TT + chunk * CSN;
    float dlast = dac[CSN - 1];

    float acc[4][8];
#pragma unroll
    for (int r = 0; r < 4; r++)
#pragma unroll
        for (int c = 0; c < 8; c++) acc[r][c] = 0.0f;

    for (int jt = 7; jt >= 0; jt--) {
        int j0 = jt * 32;
        if (dlast - dac[j0 + 31] < DEADTH) break;
        if (tid < 32)
            sw[tid] = __expf(fmaxf(dlast - dac[j0 + tid], -80.0f)) * dtp[j0 + tid];
        __syncthreads();
#pragma unroll
        for (int i = 0; i < 2; i++) {
            int f = tid + i * 256;
            int j = f >> 4, pv = (f & 15) * 4;
            float4 xv = *(const float4*)&g_xbc[(size_t)(chunk * CSN + j0 + j) * CONVD + h * PN + pv];
            float w = sw[j];
            xv.x *= w; xv.y *= w; xv.z *= w; xv.w *= w;
            *(float4*)&sxw[j][pv] = xv;
        }
#pragma unroll
        for (int i = 0; i < 4; i++) {
            int f = tid + i * 256;
            int j = f >> 5, nv = (f & 31) * 4;
            *(float4*)&sB[j][nv] =
                *(const float4*)&g_xbc[(size_t)(chunk * CSN + j0 + j) * CONVD + INTER + g * NN + nv];
        }
        __syncthreads();
#pragma unroll 2
        for (int j = 0; j < 32; j++) {
            float4 xv = *(const float4*)&sxw[j][p0];
            float4 b0 = *(const float4*)&sB[j][n0];
            float4 b1 = *(const float4*)&sB[j][n0 + 4];
            float xr[4] = {xv.x, xv.y, xv.z, xv.w};
            float bb[8] = {b0.x, b0.y, b0.z, b0.w, b1.x, b1.y, b1.z, b1.w};
#pragma unroll
            for (int r = 0; r < 4; r++)
#pragma unroll
                for (int c = 0; c < 8; c++) acc[r][c] += xr[r] * bb[c];
        }
        __syncthreads();
    }

    float* out = g_state + (size_t)(chunk * HN + h) * (PN * NN);
#pragma unroll
    for (int r = 0; r < 4; r++) {
        *(float4*)&out[(size_t)(p0 + r) * NN + n0]     = make_float4(acc[r][0], acc[r][1], acc[r][2], acc[r][3]);
        *(float4*)&out[(size_t)(p0 + r) * NN + n0 + 4] = make_float4(acc[r][4], acc[r][5], acc[r][6], acc[r][7]);
    }
}

// ============================================================
// inter-chunk scan
// ============================================================
__global__ __launch_bounds__(256) void k_scan()
{
    int b = blockIdx.x, h = blockIdx.y;
    int tid = threadIdx.x;
    float acc[32];
#pragma unroll
    for (int k = 0; k < 32; k++) acc[k] = 0.0f;
    for (int cl = 0; cl < 8; cl++) {
        int chunk = b * 8 + cl;
        size_t base = (size_t)(chunk * HN + h) * (PN * NN);
#pragma unroll
        for (int k = 0; k < 32; k++) g_prev[base + tid + k * 256] = acc[k];
        float decay = __expf(fmaxf(g_dacs[(size_t)h * TT + chunk * CSN + CSN - 1], -80.0f));
#pragma unroll
        for (int k = 0; k < 32; k++)
            acc[k] = decay * acc[k] + g_state[base + tid + k * 256];
    }
}

// ============================================================
// Y_off
// ============================================================
__global__ __launch_bounds__(256) void k_yoff()
{
    int chunk = blockIdx.x;
    if ((chunk & 7) == 0) return;
    int h = blockIdx.y, g = h >> 3;
    const float* dac = g_dacs + (size_t)h * TT + chunk * CSN;
    if (dac[0] < DEADTH) return;

    __shared__ __align__(16) float sPT[128][64];
    __shared__ __align__(16) float sC[16][128];

    int tid = threadIdx.x;
    size_t pbase = (size_t)(chunk * HN + h) * (PN * NN);
#pragma unroll
    for (int k = 0; k < 32; k++) {
        int idx = tid + k * 256;
        int p = idx >> 7, n = idx & 127;
        sPT[n][p] = g_prev[pbase + idx];
    }
    __syncthreads();

    int im = tid >> 4;
    int p0 = (tid & 15) * 4;

    for (int it = 0; it < 16; it++) {
        int i0 = it * 16;
        if (dac[i0] < DEADTH) break;
#pragma unroll
        for (int k = 0; k < 2; k++) {
            int f = tid + k * 256;
            int i = f >> 5, nv = (f & 31) * 4;
            *(float4*)&sC[i][nv] =
                *(const float4*)&g_xbc[(size_t)(chunk * CSN + i0 + i) * CONVD + INTER + GNN + g * NN + nv];
        }
        __syncthreads();
        float4 acc = make_float4(0.f, 0.f, 0.f, 0.f);
#pragma unroll 4
        for (int n = 0; n < 128; n++) {
            float cv = sC[im][n];
            float4 pv = *(const float4*)&sPT[n][p0];
            acc.x += cv * pv.x; acc.y += cv * pv.y;
            acc.z += cv * pv.z; acc.w += cv * pv.w;
        }
        float e = __expf(fmaxf(dac[i0 + im], -80.0f));
        int t = chunk * CSN + i0 + im;
        float4 o = *(float4*)&g_y[(size_t)t * INTER + h * PN + p0];
        o.x += e * acc.x; o.y += e * acc.y; o.z += e * acc.z; o.w += e * acc.w;
        *(float4*)&g_y[(size_t)t * INTER + h * PN + p0] = o;
        __syncthreads();
    }
}

// ============================================================
// RMSNorm * silu(z) gate, in place on g_y.
// Output is tf32-rna rounded AND kslot-permuted (GEMM2 A operand).
// ============================================================
__global__ __launch_bounds__(256) void k_norm(const float* __restrict__ norm_w)
{
    int t = blockIdx.x;
    int tid = threadIdx.x;
    __shared__ float red[8];
    float* yp = g_y + (size_t)t * INTER;
    const float* zp = g_zx + (size_t)t * PROJ;

    float ss = 0.0f;
#pragma unroll
    for (int k = 0; k < 16; k++) {
        float v = yp[tid + k * 256];
        ss += v * v;
    }
#pragma unroll
    for (int off = 16; off >= 1; off >>= 1) ss += __shfl_xor_sync(0xffffffffu, ss, off);
    if ((tid & 31) == 0) red[tid >> 5] = ss;
    __syncthreads();
    if (tid == 0) {
        float tot = 0.0f;
#pragma unroll
        for (int i = 0; i < 8; i++) tot += red[i];
        red[0] = rsqrtf(tot * (1.0f / INTER) + 1e-5f);
    }
    __syncthreads();
    float rinv = red[0];
#pragma unroll
    for (int k = 0; k < 16; k++) {
        int c = tid + k * 256;
        float v = yp[c];
        float z = zp[c];
        float o = norm_w[c] * v * rinv * siluf(z);
        yp[(c & ~31) | kslot(c & 31)] = __uint_as_float(f2tf(o));
    }
}

// ============================================================
// launch
// ============================================================
extern "C" void kernel_launch(void* const* d_in, const int* in_sizes, int n_in,
                              void* d_out, int out_size)
{
    const float* hidden   = (const float*)d_in[0];
    const float* in_w     = (const float*)d_in[1];
    const float* conv_w   = (const float*)d_in[2];
    const float* conv_b   = (const float*)d_in[3];
    const float* dt_bias  = (const float*)d_in[4];
    const float* A_log    = (const float*)d_in[5];
    const float* Dv       = (const float*)d_in[6];
    const float* norm_w   = (const float*)d_in[7];
    const float* out_w    = (const float*)d_in[8];
    float* outp = (float*)d_out;

    float* zx;  cudaGetSymbolAddress((void**)&zx,  g_zx);
    float* yy;  cudaGetSymbolAddress((void**)&yy,  g_y);
    float* hr;  cudaGetSymbolAddress((void**)&hr,  g_hr);
    float* w1r; cudaGetSymbolAddress((void**)&w1r, g_w1r);
    float* w2r; cudaGetSymbolAddress((void**)&w2r, g_w2r);

    static int smem_set = 0;
    const int gemm_smem = 2 * (ASTG + BSTG) * (int)sizeof(float);  // 110,592 B
    if (!smem_set) {
        cudaFuncSetAttribute(k_gemm, cudaFuncAttributeMaxDynamicSharedMemorySize, gemm_smem);
        smem_set = 1;
    }

    // 0. pre-round + k-block-permute GEMM operands
    k_round<<<2048, 256>>>(hidden, hr,  (TT * HIDD) / 4);
    k_round<<<4096, 256>>>(in_w,  w1r, (PROJ * HIDD) / 4);
    k_round<<<2048, 256>>>(out_w, w2r, (HIDD * INTER) / 4);

    // 1. in_proj:  zx[T, PROJ] = hr @ w1r^T
    {
        dim3 grid((PROJ + 255) / 256, TT / 128);
        k_gemm<<<grid, 256, gemm_smem>>>(hr, w1r, zx, PROJ, HIDD / 32, HIDD, HIDD, PROJ);
    }
    // 2. conv + silu
    k_conv<<<dim3(CONVD / 256, TT), 256>>>(conv_w, conv_b);
    // 3. dt softplus + cumsum
    k_dtscan<<<dim3(NCH, 8), 256>>>(A_log, dt_bias);
    // 4. CB
    k_cb<<<dim3(16, NCH * GN_), 256>>>();
    // 5. Y_diag + D*x
    k_ydiag<<<dim3(4, NCH, HN), 256>>>(Dv);
    // 6. states
    k_states<<<dim3(NCH, HN), 256>>>();
    // 7. scan
    k_scan<<<dim3(BB, HN), 256>>>();
    // 8. Y_off
    k_yoff<<<dim3(NCH, HN), 256>>>();
    // 9. rmsnorm + gate (writes rounded+permuted y)
    k_norm<<<TT, 256>>>(norm_w);
    // 10. out_proj: out[T, HIDD] = y @ w2r^T
    {
        dim3 grid(HIDD / 256, TT / 128);
        k_gemm<<<grid, 256, gemm_smem>>>(yy, w2r, outp, HIDD, INTER / 32, INTER, INTER, HIDD);
    }
    (void)in_sizes; (void)n_in; (void)out_size;
}